// round 6
// baseline (speedup 1.0000x reference)
#include <cuda_runtime.h>

// x [B=8, I=32, O=32, D=8, H=14, W=14, kh=3, kw=3] fp32 -> out [B, O, D, H, W] fp32
namespace {
constexpr int Bn = 8, In = 32, On = 32, Dn = 8, Hn = 14, Wn = 14, Kn = 9;
constexpr int WK    = Wn * Kn;     // 126 contiguous floats per (b,i,o,d,h)
constexpr int PK    = 12;          // padded k-stride (float4-aligned)
constexpr int PROW  = Wn * PK;     // 168 floats per d-row in smem
constexpr int SLABP = Dn * PROW;   // 1344 floats per padded slab
constexpr int NT    = 256;
constexpr int SUBK  = 26;          // ceil(0.8 * 32)
constexpr int ROPS  = 98;          // cp.async ops per d-row (7 even-w * 5 + 7 odd-w * 9)
constexpr int NOPS  = Dn * ROPS;   // 784 per slab
constexpr int XW    = 260;         // sXavg w-stride: [w][i][d8] (260*4B, 16B-aligned)
constexpr int LW    = 36;          // sNI/sLoss w-stride: [w][i] (144B, 16B-aligned)
}

__device__ __forceinline__ void cp8(void* sm, const void* gm) {
    unsigned s = (unsigned)__cvta_generic_to_shared(sm);
    asm volatile("cp.async.ca.shared.global [%0], [%1], 8;\n" :: "r"(s), "l"(gm));
}
__device__ __forceinline__ void cp4(void* sm, const void* gm) {
    unsigned s = (unsigned)__cvta_generic_to_shared(sm);
    asm volatile("cp.async.ca.shared.global [%0], [%1], 4;\n" :: "r"(s), "l"(gm));
}
__device__ __forceinline__ void cp_commit() {
    asm volatile("cp.async.commit_group;\n");
}
template <int N>
__device__ __forceinline__ void cp_wait() {
    asm volatile("cp.async.wait_group %0;\n" :: "n"(N));
}
__device__ __forceinline__ float fsqrt_ap(float x) {
    float r; asm("sqrt.approx.f32 %0, %1;" : "=f"(r) : "f"(x)); return r;
}
__device__ __forceinline__ float frcp_ap(float x) {
    float r; asm("rcp.approx.f32 %0, %1;" : "=f"(r) : "f"(x)); return r;
}
// Monotone float -> uint key: a <= b  <=>  fkey(a) <= fkey(b)
__device__ __forceinline__ unsigned fkey(float f) {
    unsigned u = __float_as_uint(f);
    return u ^ (unsigned)(((int)u >> 31) | 0x80000000);
}

__global__ void __launch_bounds__(NT, 6)
caps_route_kernel(const float* __restrict__ x, float* __restrict__ out) {
    const int h = blockIdx.x, o = blockIdx.y, b = blockIdx.z;
    const int tid = threadIdx.x;

    __shared__ __align__(16) float sl[3][SLABP];       // cp.async ring, k padded to 12
    __shared__ __align__(16) float sNorm[PROW];        // [w*12 + k], pads = 0
    __shared__ __align__(16) float sXavg[Wn * XW];     // [w][i][d8] (w-stride 260)
    __shared__ __align__(16) float sNI[Wn * LW];       // [w][i]
    __shared__ __align__(16) float sLoss[Wn * LW];     // [w][i]
    __shared__ __align__(16) float sV[Wn * Dn];        // [w][d]
    __shared__ float    sRsum[Wn];
    __shared__ unsigned sThr[Wn];
    __shared__ float    sRfin[Wn];

    const long strideD = (long)Hn * Wn * Kn;           // 1764
    const long strideO = Dn * strideD;                 // 14112
    const long strideI = On * strideO;                 // 451584
    const long strideB = In * strideI;                 // 14450688
    const float* base = x + (long)b * strideB + (long)o * strideO + (long)h * WK;

    // ---- cp.async op table (<=4 ops/thread, fixed across slabs) ----
    // even w: 4 x 8B (k=0,2,4,6) + 1 x 4B (k=8); odd w: 9 x 4B
    int gO[4], sO[4]; bool e8[4];
    #pragma unroll
    for (int q = 0; q < 4; ++q) {
        int j = tid + q * NT;
        if (j < NOPS) {
            int r = j / ROPS, m = j - ROPS * r;
            int w, k; bool is8;
            if (m < 35) {
                int we = m / 5, m5 = m - 5 * we;
                w = 2 * we;
                if (m5 < 4) { k = 2 * m5; is8 = true; }
                else        { k = 8;      is8 = false; }
            } else {
                int m2 = m - 35, wo = m2 / 9;
                w = 2 * wo + 1; k = m2 - 9 * wo; is8 = false;
            }
            gO[q] = r * (int)strideD + 9 * w + k;
            sO[q] = r * PROW + PK * w + k;
            e8[q] = is8;
        }
    }
    const bool hasQ3 = (tid < NOPS - 3 * NT);   // tid < 16

    auto prefetch = [&](int slab, float* buf) {
        const float* g = base + (long)slab * strideI;
        if (e8[0]) cp8(buf + sO[0], g + gO[0]); else cp4(buf + sO[0], g + gO[0]);
        if (e8[1]) cp8(buf + sO[1], g + gO[1]); else cp4(buf + sO[1], g + gO[1]);
        if (e8[2]) cp8(buf + sO[2], g + gO[2]); else cp4(buf + sO[2], g + gO[2]);
        if (hasQ3) {
            if (e8[3]) cp8(buf + sO[3], g + gO[3]); else cp4(buf + sO[3], g + gO[3]);
        }
    };

    // Region A: 42 threads, (w, kq): norms of 4 k's at a time (pads masked)
    const bool actA = (tid < Wn * 3);
    const int wA = tid / 3, kqA = tid - 3 * wA;
    // Region C: 112 threads, (d, w)
    const bool actC = (tid < Dn * Wn);
    const int dC = tid / Wn, wC = tid - Wn * dC;

    prefetch(0, sl[0]); cp_commit();
    prefetch(1, sl[1]); cp_commit();
    if (tid < Wn) sThr[tid] = 0u;

    int bufi = 0;
    // ---- Phase 1 ----
    for (int i = 0; i < In; ++i) {
        cp_wait<1>();
        __syncthreads();

        if (i + 2 < In) {
            int nb = bufi + 2; if (nb >= 3) nb -= 3;
            prefetch(i + 2, sl[nb]);
        }
        cp_commit();

        const float* s = sl[bufi];

        if (actA) {   // norms over D for 4 consecutive k
            float4 ssq = {0.f, 0.f, 0.f, 0.f};
            const float* p0 = s + wA * PK + 4 * kqA;
            #pragma unroll
            for (int d = 0; d < Dn; ++d) {
                float4 v = *(const float4*)(p0 + d * PROW);
                ssq.x += v.x * v.x; ssq.y += v.y * v.y;
                ssq.z += v.z * v.z; ssq.w += v.w * v.w;
            }
            float4 nr;
            nr.x = fsqrt_ap(ssq.x); nr.y = fsqrt_ap(ssq.y);
            nr.z = fsqrt_ap(ssq.z); nr.w = fsqrt_ap(ssq.w);
            if (kqA == 2) { nr.y = 0.f; nr.z = 0.f; nr.w = 0.f; }  // k=9..11 pads
            *(float4*)(sNorm + wA * PK + 4 * kqA) = nr;
        }
        __syncthreads();

        if (actC) {   // xavg[d][w]
            const float* sp = s + dC * PROW + wC * PK;
            float4 x0 = *(const float4*)(sp);
            float4 x1 = *(const float4*)(sp + 4);
            float  x8 = sp[8];
            const float* np = sNorm + wC * PK;
            float4 n0 = *(const float4*)(np);
            float4 n1 = *(const float4*)(np + 4);
            float  n8 = np[8];
            float num = n0.x*x0.x + n0.y*x0.y + n0.z*x0.z + n0.w*x0.w
                      + n1.x*x1.x + n1.y*x1.y + n1.z*x1.z + n1.w*x1.w + n8*x8;
            float den = n0.x + n0.y + n0.z + n0.w
                      + n1.x + n1.y + n1.z + n1.w + n8;
            sXavg[wC * XW + i * Dn + dC] = num * frcp_ap(den);
        }
        ++bufi; if (bufi == 3) bufi = 0;
    }
    __syncthreads();

    // ---- Phase 2 ----
    // nI[w][i] = || xavg[w][i][:] ||
    for (int p = tid; p < In * Wn; p += NT) {
        int w = p >> 5, i = p & 31;
        const float* xp = sXavg + w * XW + i * Dn;
        float4 lo = *(const float4*)(xp), hi = *(const float4*)(xp + 4);
        float s2 = lo.x*lo.x + lo.y*lo.y + lo.z*lo.z + lo.w*lo.w
                 + hi.x*hi.x + hi.y*hi.y + hi.z*hi.z + hi.w*hi.w;
        sNI[w * LW + i] = fsqrt_ap(s2);
    }
    __syncthreads();

    if (tid < Wn) {   // 1 / sum_i nI
        float sum = 0.f;
        #pragma unroll
        for (int q = 0; q < 8; ++q) {
            float4 v = *(const float4*)(sNI + tid * LW + 4 * q);
            sum += v.x + v.y + v.z + v.w;
        }
        sRsum[tid] = frcp_ap(sum);
    }
    __syncthreads();

    if (tid < 28) {   // consensus v[w][d], half of d per thread
        int w = tid >> 1, hf = tid & 1;
        float4 acc = {0.f, 0.f, 0.f, 0.f};
        #pragma unroll 8
        for (int i = 0; i < In; ++i) {
            float n = sNI[w * LW + i];
            float4 xv = *(const float4*)(sXavg + w * XW + i * Dn + 4 * hf);
            acc.x += n * xv.x; acc.y += n * xv.y;
            acc.z += n * xv.z; acc.w += n * xv.w;
        }
        float r = sRsum[w];
        float4 v = {acc.x * r, acc.y * r, acc.z * r, acc.w * r};
        *(float4*)(sV + w * Dn + 4 * hf) = v;
    }
    __syncthreads();

    // losses[w][i] = -<v[w], xavg[w][i]>
    for (int p = tid; p < In * Wn; p += NT) {
        int w = p >> 5, i = p & 31;
        const float* xp = sXavg + w * XW + i * Dn;
        float4 lo = *(const float4*)(xp), hi = *(const float4*)(xp + 4);
        float4 vl = *(const float4*)(sV + w * Dn);
        float4 vh = *(const float4*)(sV + w * Dn + 4);
        sLoss[w * LW + i] = -(vl.x*lo.x + vl.y*lo.y + vl.z*lo.z + vl.w*lo.w
                            + vh.x*hi.x + vh.y*hi.y + vh.z*hi.z + vh.w*hi.w);
    }
    __syncthreads();

    // kth-smallest threshold: thr = max{ v : #(x < v) <= SUBK-1 } == sorted[SUBK-1]
    if (tid < Dn * Wn) {
        int w = tid >> 3, iq = tid & 7;
        float4 cand = *(const float4*)(sLoss + w * LW + 4 * iq);
        int c0 = 0, c1 = 0, c2 = 0, c3 = 0;
        #pragma unroll
        for (int j = 0; j < 8; ++j) {
            float4 J = *(const float4*)(sLoss + w * LW + 4 * j);
            c0 += (J.x < cand.x) + (J.y < cand.x) + (J.z < cand.x) + (J.w < cand.x);
            c1 += (J.x < cand.y) + (J.y < cand.y) + (J.z < cand.y) + (J.w < cand.y);
            c2 += (J.x < cand.z) + (J.y < cand.z) + (J.z < cand.z) + (J.w < cand.z);
            c3 += (J.x < cand.w) + (J.y < cand.w) + (J.z < cand.w) + (J.w < cand.w);
        }
        if (c0 <= SUBK - 1) atomicMax(&sThr[w], fkey(cand.x));
        if (c1 <= SUBK - 1) atomicMax(&sThr[w], fkey(cand.y));
        if (c2 <= SUBK - 1) atomicMax(&sThr[w], fkey(cand.z));
        if (c3 <= SUBK - 1) atomicMax(&sThr[w], fkey(cand.w));
    }
    __syncthreads();

    if (tid < Wn) {   // masked denominator reciprocal
        const unsigned t = sThr[tid];
        float den = 0.f;
        #pragma unroll
        for (int q = 0; q < 8; ++q) {
            float4 L = *(const float4*)(sLoss + tid * LW + 4 * q);
            float4 N = *(const float4*)(sNI  + tid * LW + 4 * q);
            den += (fkey(L.x) <= t ? N.x : 0.f) + (fkey(L.y) <= t ? N.y : 0.f)
                 + (fkey(L.z) <= t ? N.z : 0.f) + (fkey(L.w) <= t ? N.w : 0.f);
        }
        sRfin[tid] = frcp_ap(den);
    }
    __syncthreads();

    if (tid < 28) {   // masked re-average + store
        int w = tid >> 1, hf = tid & 1;
        const unsigned t = sThr[w];
        float4 acc = {0.f, 0.f, 0.f, 0.f};
        #pragma unroll 8
        for (int i = 0; i < In; ++i) {
            float l = sLoss[w * LW + i];
            float n = (fkey(l) <= t) ? sNI[w * LW + i] : 0.f;
            float4 xv = *(const float4*)(sXavg + w * XW + i * Dn + 4 * hf);
            acc.x += n * xv.x; acc.y += n * xv.y;
            acc.z += n * xv.z; acc.w += n * xv.w;
        }
        const float rf = sRfin[w];
        const long ob = ((long)b * On + o) * Dn;
        float vals[4] = {acc.x * rf, acc.y * rf, acc.z * rf, acc.w * rf};
        #pragma unroll
        for (int c = 0; c < 4; ++c) {
            int d = 4 * hf + c;
            out[(ob + d) * (Hn * Wn) + h * Wn + w] = vals[c];
        }
    }
}

extern "C" void kernel_launch(void* const* d_in, const int* in_sizes, int n_in,
                              void* d_out, int out_size) {
    const float* x = (const float*)d_in[0];
    float* out = (float*)d_out;
    dim3 grid(Hn, On, Bn);   // 14 x 32 x 8 = 3584 CTAs
    caps_route_kernel<<<grid, NT>>>(x, out);
}

// round 7
// speedup vs baseline: 1.1574x; 1.1574x over previous
#include <cuda_runtime.h>

// x [B=8, I=32, O=32, D=8, H=14, W=14, kh=3, kw=3] fp32 -> out [B, O, D, H, W] fp32
namespace {
constexpr int Bn = 8, In = 32, On = 32, Dn = 8, Hn = 14, Wn = 14, Kn = 9;
constexpr int WK   = Wn * Kn;          // 126 positions per (d) row
constexpr int NT   = 256;
constexpr int SUBK = 26;               // ceil(0.8 * 32)
constexpr int PROW = 132;              // product row stride (conflict-free)
constexpr int WBUF = Dn * PROW + 128;  // per-warp buffer: products 1056 + n 128 = 1184 floats
constexpr int XW   = 260;              // sXavg w-stride: [w][i][d8] (16B-aligned)
constexpr int LW   = 36;               // sNI/sLoss w-stride: [w][i]
constexpr int SMEM_DYN = (8 * WBUF + Wn * XW) * 4;   // 37888 + 14560 = 52448 B
}

__device__ __forceinline__ float fsqrt_ap(float x) {
    float r; asm("sqrt.approx.f32 %0, %1;" : "=f"(r) : "f"(x)); return r;
}
__device__ __forceinline__ float frcp_ap(float x) {
    float r; asm("rcp.approx.f32 %0, %1;" : "=f"(r) : "f"(x)); return r;
}
// Monotone float -> uint key: a <= b  <=>  fkey(a) <= fkey(b)
__device__ __forceinline__ unsigned fkey(float f) {
    unsigned u = __float_as_uint(f);
    return u ^ (unsigned)(((int)u >> 31) | 0x80000000);
}

__global__ void __launch_bounds__(NT)
caps_route_kernel(const float* __restrict__ x, float* __restrict__ out) {
    const int h = blockIdx.x, o = blockIdx.y, b = blockIdx.z;
    const int tid = threadIdx.x;
    const int lane = tid & 31, wrp = tid >> 5;

    extern __shared__ __align__(16) float dyn[];
    float* __restrict__ sWb   = dyn;               // [8][WBUF] warp-private
    float* __restrict__ sXavg = dyn + 8 * WBUF;    // [w][i][d8], w-stride XW

    __shared__ __align__(16) float sNI[Wn * LW];   // [w][i]
    __shared__ __align__(16) float sLoss[Wn * LW]; // [w][i]
    __shared__ __align__(16) float sV[Wn * Dn];    // [w][d]
    __shared__ float    sRsum[Wn];
    __shared__ unsigned sThr[Wn];
    __shared__ float    sRfin[Wn];

    const long strideD = (long)Hn * Wn * Kn;       // 1764
    const long strideO = Dn * strideD;             // 14112
    const long strideI = On * strideO;             // 451584
    const long strideB = In * strideI;             // 14450688
    const float* base = x + (long)b * strideB + (long)o * strideO + (long)h * WK;

    float* __restrict__ P = sWb + wrp * WBUF;      // products [d*132 + p]
    float* __restrict__ N = P + Dn * PROW;         // norms [p]

    if (tid < Wn) sThr[tid] = 0u;

    // ---- Phase 1: warp-autonomous, each warp owns capsules wrp + 8c ----
    float xd[4][Dn];   // registers for one slab: [round][d], p = 32r + lane

    // initial load: capsule i = wrp
    {
        const float* g = base + (long)wrp * strideI;
        #pragma unroll
        for (int r = 0; r < 4; ++r) {
            const int p = 32 * r + lane;
            const bool v = (p < WK);
            #pragma unroll
            for (int d = 0; d < Dn; ++d)
                xd[r][d] = v ? g[d * strideD + p] : 0.f;
        }
    }

    #pragma unroll
    for (int c = 0; c < 4; ++c) {
        const int i = wrp + 8 * c;

        // produce: norms + product stores (conflict-free, warp-private)
        #pragma unroll
        for (int r = 0; r < 4; ++r) {
            const int p = 32 * r + lane;
            float ss = 0.f;
            #pragma unroll
            for (int d = 0; d < Dn; ++d) ss += xd[r][d] * xd[r][d];
            const float nv = fsqrt_ap(ss);
            if (p < WK) {
                N[p] = nv;
                #pragma unroll
                for (int d = 0; d < Dn; ++d)
                    P[d * PROW + p] = nv * xd[r][d];
            }
        }

        // prefetch next capsule's slab into registers (hidden under consume)
        if (c < 3) {
            const float* g = base + (long)(i + 8) * strideI;
            #pragma unroll
            for (int r = 0; r < 4; ++r) {
                const int p = 32 * r + lane;
                const bool v = (p < WK);
                #pragma unroll
                for (int d = 0; d < Dn; ++d)
                    xd[r][d] = v ? g[d * strideD + p] : 0.f;
            }
        }
        __syncwarp();

        // consume: xavg[d][w] = (sum_k n*x) / (sum_k n)
        #pragma unroll
        for (int r2 = 0; r2 < 4; ++r2) {
            const int q = 32 * r2 + lane;
            if (q < Dn * Wn) {
                const int d = q & 7, w = q >> 3;
                const float* pp = P + d * PROW + 9 * w;
                const float* nn = N + 9 * w;
                float num = 0.f, den = 0.f;
                #pragma unroll
                for (int k = 0; k < Kn; ++k) {
                    num += pp[k];
                    den += nn[k];
                }
                sXavg[w * XW + i * Dn + d] = num * frcp_ap(den);
            }
        }
        __syncwarp();   // done reading P/N before next capsule overwrites
    }
    __syncthreads();

    // ---- Phase 2: reductions over input capsules (float4 throughout) ----
    // nI[w][i] = || xavg[w][i][:] ||
    for (int p = tid; p < In * Wn; p += NT) {
        int w = p >> 5, i = p & 31;
        const float* xp = sXavg + w * XW + i * Dn;
        float4 lo = *(const float4*)(xp), hi = *(const float4*)(xp + 4);
        float s2 = lo.x*lo.x + lo.y*lo.y + lo.z*lo.z + lo.w*lo.w
                 + hi.x*hi.x + hi.y*hi.y + hi.z*hi.z + hi.w*hi.w;
        sNI[w * LW + i] = fsqrt_ap(s2);
    }
    __syncthreads();

    if (tid < Wn) {   // 1 / sum_i nI
        float sum = 0.f;
        #pragma unroll
        for (int q = 0; q < 8; ++q) {
            float4 v = *(const float4*)(sNI + tid * LW + 4 * q);
            sum += v.x + v.y + v.z + v.w;
        }
        sRsum[tid] = frcp_ap(sum);
    }
    __syncthreads();

    if (tid < 28) {   // consensus v[w][d], half of d per thread
        int w = tid >> 1, hf = tid & 1;
        float4 acc = {0.f, 0.f, 0.f, 0.f};
        #pragma unroll 8
        for (int i = 0; i < In; ++i) {
            float n = sNI[w * LW + i];
            float4 xv = *(const float4*)(sXavg + w * XW + i * Dn + 4 * hf);
            acc.x += n * xv.x; acc.y += n * xv.y;
            acc.z += n * xv.z; acc.w += n * xv.w;
        }
        float r = sRsum[w];
        float4 v = {acc.x * r, acc.y * r, acc.z * r, acc.w * r};
        *(float4*)(sV + w * Dn + 4 * hf) = v;
    }
    __syncthreads();

    // losses[w][i] = -<v[w], xavg[w][i]>
    for (int p = tid; p < In * Wn; p += NT) {
        int w = p >> 5, i = p & 31;
        const float* xp = sXavg + w * XW + i * Dn;
        float4 lo = *(const float4*)(xp), hi = *(const float4*)(xp + 4);
        float4 vl = *(const float4*)(sV + w * Dn);
        float4 vh = *(const float4*)(sV + w * Dn + 4);
        sLoss[w * LW + i] = -(vl.x*lo.x + vl.y*lo.y + vl.z*lo.z + vl.w*lo.w
                            + vh.x*hi.x + vh.y*hi.y + vh.z*hi.z + vh.w*hi.w);
    }
    __syncthreads();

    // kth-smallest threshold: thr = max{ v : #(x < v) <= SUBK-1 } == sorted[SUBK-1]
    if (tid < Dn * Wn) {
        int w = tid >> 3, iq = tid & 7;
        float4 cand = *(const float4*)(sLoss + w * LW + 4 * iq);
        int c0 = 0, c1 = 0, c2 = 0, c3 = 0;
        #pragma unroll
        for (int j = 0; j < 8; ++j) {
            float4 J = *(const float4*)(sLoss + w * LW + 4 * j);
            c0 += (J.x < cand.x) + (J.y < cand.x) + (J.z < cand.x) + (J.w < cand.x);
            c1 += (J.x < cand.y) + (J.y < cand.y) + (J.z < cand.y) + (J.w < cand.y);
            c2 += (J.x < cand.z) + (J.y < cand.z) + (J.z < cand.z) + (J.w < cand.z);
            c3 += (J.x < cand.w) + (J.y < cand.w) + (J.z < cand.w) + (J.w < cand.w);
        }
        if (c0 <= SUBK - 1) atomicMax(&sThr[w], fkey(cand.x));
        if (c1 <= SUBK - 1) atomicMax(&sThr[w], fkey(cand.y));
        if (c2 <= SUBK - 1) atomicMax(&sThr[w], fkey(cand.z));
        if (c3 <= SUBK - 1) atomicMax(&sThr[w], fkey(cand.w));
    }
    __syncthreads();

    if (tid < Wn) {   // masked denominator reciprocal
        const unsigned t = sThr[tid];
        float den = 0.f;
        #pragma unroll
        for (int q = 0; q < 8; ++q) {
            float4 L = *(const float4*)(sLoss + tid * LW + 4 * q);
            float4 Nv = *(const float4*)(sNI + tid * LW + 4 * q);
            den += (fkey(L.x) <= t ? Nv.x : 0.f) + (fkey(L.y) <= t ? Nv.y : 0.f)
                 + (fkey(L.z) <= t ? Nv.z : 0.f) + (fkey(L.w) <= t ? Nv.w : 0.f);
        }
        sRfin[tid] = frcp_ap(den);
    }
    __syncthreads();

    if (tid < 28) {   // masked re-average + store
        int w = tid >> 1, hf = tid & 1;
        const unsigned t = sThr[w];
        float4 acc = {0.f, 0.f, 0.f, 0.f};
        #pragma unroll 8
        for (int i = 0; i < In; ++i) {
            float l = sLoss[w * LW + i];
            float n = (fkey(l) <= t) ? sNI[w * LW + i] : 0.f;
            float4 xv = *(const float4*)(sXavg + w * XW + i * Dn + 4 * hf);
            acc.x += n * xv.x; acc.y += n * xv.y;
            acc.z += n * xv.z; acc.w += n * xv.w;
        }
        const float rf = sRfin[w];
        const long ob = ((long)b * On + o) * Dn;
        float vals[4] = {acc.x * rf, acc.y * rf, acc.z * rf, acc.w * rf};
        #pragma unroll
        for (int cc = 0; cc < 4; ++cc) {
            int d = 4 * hf + cc;
            out[(ob + d) * (Hn * Wn) + h * Wn + w] = vals[cc];
        }
    }
}

extern "C" void kernel_launch(void* const* d_in, const int* in_sizes, int n_in,
                              void* d_out, int out_size) {
    const float* x = (const float*)d_in[0];
    float* out = (float*)d_out;
    cudaFuncSetAttribute(caps_route_kernel,
                         cudaFuncAttributeMaxDynamicSharedMemorySize, SMEM_DYN);
    dim3 grid(Hn, On, Bn);   // 14 x 32 x 8 = 3584 CTAs
    caps_route_kernel<<<grid, NT, SMEM_DYN>>>(x, out);
}

// round 9
// speedup vs baseline: 1.3077x; 1.1298x over previous
#include <cuda_runtime.h>

// x [B=8, I=32, O=32, D=8, H=14, W=14, kh=3, kw=3] fp32 -> out [B, O, D, H, W] fp32
namespace {
constexpr int Bn = 8, In = 32, On = 32, Dn = 8, Hn = 14, Wn = 14, Kn = 9;
constexpr int WK   = Wn * Kn;          // 126 positions
constexpr int NT   = 256;
constexpr int SUBK = 26;               // ceil(0.8 * 32)
constexpr int PCH  = 66;               // per-chunk product row stride (63 + 3 pad)
constexpr int WBUF = Dn * PCH + 128;   // per-warp: products 528 + norms 128 = 656 floats
constexpr int XW   = 260;              // sXavg w-stride: [w][i][d8] (16B-aligned)
constexpr int LW   = 36;               // sNI/sLoss w-stride: [w][i]
}

__device__ __forceinline__ float fsqrt_ap(float x) {
    float r; asm("sqrt.approx.f32 %0, %1;" : "=f"(r) : "f"(x)); return r;
}
__device__ __forceinline__ float frcp_ap(float x) {
    float r; asm("rcp.approx.f32 %0, %1;" : "=f"(r) : "f"(x)); return r;
}
__device__ __forceinline__ void pfL2(const void* p) {
    asm volatile("prefetch.global.L2 [%0];" :: "l"(p));
}
// Monotone float -> uint key: a <= b  <=>  fkey(a) <= fkey(b)
__device__ __forceinline__ unsigned fkey(float f) {
    unsigned u = __float_as_uint(f);
    return u ^ (unsigned)(((int)u >> 31) | 0x80000000);
}

__global__ void __launch_bounds__(NT, 5)
caps_route_kernel(const float* __restrict__ x, float* __restrict__ out) {
    const int h = blockIdx.x, o = blockIdx.y, b = blockIdx.z;
    const int tid = threadIdx.x;
    const int lane = tid & 31, wrp = tid >> 5;

    __shared__ __align__(16) float sWb[8][WBUF];   // warp-private: P-chunk + norms
    __shared__ __align__(16) float sXavg[Wn * XW]; // [w][i][d8]
    __shared__ __align__(16) float sNI[Wn * LW];   // [w][i]
    __shared__ __align__(16) float sLoss[Wn * LW]; // [w][i]
    __shared__ __align__(16) float sV[Wn * Dn];    // [w][d]
    __shared__ float    sRsum[Wn];
    __shared__ unsigned sThr[Wn];
    __shared__ float    sRfin[Wn];

    const long strideD = (long)Hn * Wn * Kn;       // 1764
    const long strideO = Dn * strideD;             // 14112
    const long strideI = On * strideO;             // 451584
    const long strideB = In * strideI;             // 14450688
    const float* base = x + (long)b * strideB + (long)o * strideO + (long)h * WK;

    float* __restrict__ P = sWb[wrp];              // products [d*66 + q], q = p - 63*chunk
    float* __restrict__ N = P + Dn * PCH;          // norms [p] (full 126)

    // consumer coords: per chunk 56 positions = (d, wl), wl in [0,7)
    const int q0 = lane;               // round 0
    const int q1 = 32 + lane;          // round 1 (valid if < 56)
    const int wl0 = q0 % 7, dd0 = q0 / 7;
    const bool a1 = (q1 < 56);
    const int wl1 = q1 % 7, dd1 = q1 / 7;
    // prefetch coords: lane covers (d = lane>>2, 128B chunk c = lane&3)
    const long pfOff = (long)(lane >> 2) * strideD + 32 * (lane & 3);

    if (tid < Wn) sThr[tid] = 0u;

    // ---- Phase 1: warp-autonomous; warp owns capsules wrp + 8c ----
    #pragma unroll
    for (int c = 0; c < 4; ++c) {
        const int i = wrp + 8 * c;
        const float* g = base + (long)i * strideI;

        if (c < 3)   // keep HBM busy: fire L2 prefetch for next capsule's slab
            pfL2(base + (long)(i + 8) * strideI + pfOff);

        #pragma unroll
        for (int ch = 0; ch < 2; ++ch) {
            // produce: positions p in [63*ch, 63*ch+63)
            #pragma unroll
            for (int p0 = 0; p0 < 63; p0 += 32) {
                const int q = p0 + lane;
                if (q < 63) {
                    const int p = 63 * ch + q;
                    float xv[Dn];
                    #pragma unroll
                    for (int d = 0; d < Dn; ++d) xv[d] = g[d * strideD + p];
                    float ss = 0.f;
                    #pragma unroll
                    for (int d = 0; d < Dn; ++d) ss += xv[d] * xv[d];
                    const float nv = fsqrt_ap(ss);
                    N[p] = nv;
                    #pragma unroll
                    for (int d = 0; d < Dn; ++d)
                        P[d * PCH + q] = nv * xv[d];
                }
            }
            __syncwarp();

            // consume: xavg for w in [7*ch, 7*ch+7)
            {
                const int nb = 63 * ch;
                {   // round 0 (q0 always < 56)
                    const float* pp = P + dd0 * PCH + 9 * wl0;
                    const float* nn = N + nb + 9 * wl0;
                    float num = 0.f, den = 0.f;
                    #pragma unroll
                    for (int k = 0; k < Kn; ++k) { num += pp[k]; den += nn[k]; }
                    sXavg[(7 * ch + wl0) * XW + i * Dn + dd0] = num * frcp_ap(den);
                }
                if (a1) {
                    const float* pp = P + dd1 * PCH + 9 * wl1;
                    const float* nn = N + nb + 9 * wl1;
                    float num = 0.f, den = 0.f;
                    #pragma unroll
                    for (int k = 0; k < Kn; ++k) { num += pp[k]; den += nn[k]; }
                    sXavg[(7 * ch + wl1) * XW + i * Dn + dd1] = num * frcp_ap(den);
                }
            }
            __syncwarp();   // P reused by next chunk / capsule
        }
    }
    __syncthreads();

    // ---- Phase 2: reductions over input capsules (float4 throughout) ----
    // nI[w][i] = || xavg[w][i][:] ||
    for (int p = tid; p < In * Wn; p += NT) {
        int w = p >> 5, i = p & 31;
        const float* xp = sXavg + w * XW + i * Dn;
        float4 lo = *(const float4*)(xp), hi = *(const float4*)(xp + 4);
        float s2 = lo.x*lo.x + lo.y*lo.y + lo.z*lo.z + lo.w*lo.w
                 + hi.x*hi.x + hi.y*hi.y + hi.z*hi.z + hi.w*hi.w;
        sNI[w * LW + i] = fsqrt_ap(s2);
    }
    __syncthreads();

    if (tid < Wn) {   // 1 / sum_i nI
        float sum = 0.f;
        #pragma unroll
        for (int q = 0; q < 8; ++q) {
            float4 v = *(const float4*)(sNI + tid * LW + 4 * q);
            sum += v.x + v.y + v.z + v.w;
        }
        sRsum[tid] = frcp_ap(sum);
    }
    __syncthreads();

    if (tid < 28) {   // consensus v[w][d]
        int w = tid >> 1, hf = tid & 1;
        float4 acc = {0.f, 0.f, 0.f, 0.f};
        #pragma unroll 8
        for (int i = 0; i < In; ++i) {
            float n = sNI[w * LW + i];
            float4 xv = *(const float4*)(sXavg + w * XW + i * Dn + 4 * hf);
            acc.x += n * xv.x; acc.y += n * xv.y;
            acc.z += n * xv.z; acc.w += n * xv.w;
        }
        float r = sRsum[w];
        float4 v = {acc.x * r, acc.y * r, acc.z * r, acc.w * r};
        *(float4*)(sV + w * Dn + 4 * hf) = v;
    }
    __syncthreads();

    // losses[w][i] = -<v[w], xavg[w][i]>
    for (int p = tid; p < In * Wn; p += NT) {
        int w = p >> 5, i = p & 31;
        const float* xp = sXavg + w * XW + i * Dn;
        float4 lo = *(const float4*)(xp), hi = *(const float4*)(xp + 4);
        float4 vl = *(const float4*)(sV + w * Dn);
        float4 vh = *(const float4*)(sV + w * Dn + 4);
        sLoss[w * LW + i] = -(vl.x*lo.x + vl.y*lo.y + vl.z*lo.z + vl.w*lo.w
                            + vh.x*hi.x + vh.y*hi.y + vh.z*hi.z + vh.w*hi.w);
    }
    __syncthreads();

    // kth-smallest threshold: thr = max{ v : #(x < v) <= SUBK-1 } == sorted[SUBK-1]
    if (tid < Dn * Wn) {
        int w = tid >> 3, iq = tid & 7;
        float4 cand = *(const float4*)(sLoss + w * LW + 4 * iq);
        int c0 = 0, c1 = 0, c2 = 0, c3 = 0;
        #pragma unroll
        for (int j = 0; j < 8; ++j) {
            float4 J = *(const float4*)(sLoss + w * LW + 4 * j);
            c0 += (J.x < cand.x) + (J.y < cand.x) + (J.z < cand.x) + (J.w < cand.x);
            c1 += (J.x < cand.y) + (J.y < cand.y) + (J.z < cand.y) + (J.w < cand.y);
            c2 += (J.x < cand.z) + (J.y < cand.z) + (J.z < cand.z) + (J.w < cand.z);
            c3 += (J.x < cand.w) + (J.y < cand.w) + (J.z < cand.w) + (J.w < cand.w);
        }
        if (c0 <= SUBK - 1) atomicMax(&sThr[w], fkey(cand.x));
        if (c1 <= SUBK - 1) atomicMax(&sThr[w], fkey(cand.y));
        if (c2 <= SUBK - 1) atomicMax(&sThr[w], fkey(cand.z));
        if (c3 <= SUBK - 1) atomicMax(&sThr[w], fkey(cand.w));
    }
    __syncthreads();

    if (tid < Wn) {   // masked denominator reciprocal
        const unsigned t = sThr[tid];
        float den = 0.f;
        #pragma unroll
        for (int q = 0; q < 8; ++q) {
            float4 L = *(const float4*)(sLoss + tid * LW + 4 * q);
            float4 Nv = *(const float4*)(sNI + tid * LW + 4 * q);
            den += (fkey(L.x) <= t ? Nv.x : 0.f) + (fkey(L.y) <= t ? Nv.y : 0.f)
                 + (fkey(L.z) <= t ? Nv.z : 0.f) + (fkey(L.w) <= t ? Nv.w : 0.f);
        }
        sRfin[tid] = frcp_ap(den);
    }
    __syncthreads();

    if (tid < 28) {   // masked re-average + store
        int w = tid >> 1, hf = tid & 1;
        const unsigned t = sThr[w];
        float4 acc = {0.f, 0.f, 0.f, 0.f};
        #pragma unroll 8
        for (int i = 0; i < In; ++i) {
            float l = sLoss[w * LW + i];
            float n = (fkey(l) <= t) ? sNI[w * LW + i] : 0.f;
            float4 xv = *(const float4*)(sXavg + w * XW + i * Dn + 4 * hf);
            acc.x += n * xv.x; acc.y += n * xv.y;
            acc.z += n * xv.z; acc.w += n * xv.w;
        }
        const float rf = sRfin[w];
        const long ob = ((long)b * On + o) * Dn;
        float vals[4] = {acc.x * rf, acc.y * rf, acc.z * rf, acc.w * rf};
        #pragma unroll
        for (int cc = 0; cc < 4; ++cc) {
            int d = 4 * hf + cc;
            out[(ob + d) * (Hn * Wn) + h * Wn + w] = vals[cc];
        }
    }
}

extern "C" void kernel_launch(void* const* d_in, const int* in_sizes, int n_in,
                              void* d_out, int out_size) {
    const float* x = (const float*)d_in[0];
    float* out = (float*)d_out;
    dim3 grid(Hn, On, Bn);   // 14 x 32 x 8 = 3584 CTAs
    caps_route_kernel<<<grid, NT>>>(x, out);
}

// round 12
// speedup vs baseline: 1.3363x; 1.0219x over previous
#include <cuda_runtime.h>

// x [B=8, I=32, O=32, D=8, H=14, W=14, kh=3, kw=3] fp32 -> out [B, O, D, H, W] fp32
namespace {
constexpr int Bn = 8, In = 32, On = 32, Dn = 8, Hn = 14, Wn = 14, Kn = 9;
constexpr int WK   = Wn * Kn;          // 126 positions
constexpr int NT   = 256;
constexpr int SUBK = 26;               // ceil(0.8 * 32)
constexpr int PR   = 88;               // P row stride per d (7w * 12k + 4 pad)
constexpr int NSZ  = 84;               // norms per chunk (12*6+8 max -> 84)
constexpr int WBUF = Dn * PR + NSZ;    // 704 + 84 = 788 floats per warp
constexpr int XW   = 260;              // sXavg w-stride: [w][i][d8] (16B-aligned)
constexpr int LW   = 36;               // sNI/sLoss w-stride: [w][i]
}

__device__ __forceinline__ float fsqrt_ap(float x) {
    float r; asm("sqrt.approx.f32 %0, %1;" : "=f"(r) : "f"(x)); return r;
}
__device__ __forceinline__ float frcp_ap(float x) {
    float r; asm("rcp.approx.f32 %0, %1;" : "=f"(r) : "f"(x)); return r;
}
__device__ __forceinline__ void pfL2(const void* p) {
    asm volatile("prefetch.global.L2 [%0];" :: "l"(p));
}
// Monotone float -> uint key: a <= b  <=>  fkey(a) <= fkey(b)
__device__ __forceinline__ unsigned fkey(float f) {
    unsigned u = __float_as_uint(f);
    return u ^ (unsigned)(((int)u >> 31) | 0x80000000);
}
__device__ __forceinline__ float sum9(const float* p) {   // 2 x LDS.128 + 1 scalar
    float4 a = *(const float4*)(p);
    float4 b = *(const float4*)(p + 4);
    return a.x + a.y + a.z + a.w + b.x + b.y + b.z + b.w + p[8];
}

__global__ void __launch_bounds__(NT, 5)
caps_route_kernel(const float* __restrict__ x, float* __restrict__ out) {
    const int h = blockIdx.x, o = blockIdx.y, b = blockIdx.z;
    const int tid = threadIdx.x;
    const int lane = tid & 31, wrp = tid >> 5;

    __shared__ __align__(16) float sWb[8][WBUF];   // warp-private: P (d-major) + N
    __shared__ __align__(16) float sXavg[Wn * XW]; // [w][i][d8]
    __shared__ __align__(16) float sNI[Wn * LW];   // [w][i]
    __shared__ __align__(16) float sLoss[Wn * LW]; // [w][i]
    __shared__ __align__(16) float sV[Wn * Dn];    // [w][d]
    __shared__ float    sRsum[Wn];
    __shared__ unsigned sThr[Wn];
    __shared__ float    sRfin[Wn];

    const long strideD = (long)Hn * Wn * Kn;       // 1764
    const long strideO = Dn * strideD;             // 14112
    const long strideI = On * strideO;             // 451584
    const long strideB = In * strideI;             // 14450688
    const float* base = x + (long)b * strideB + (long)o * strideO + (long)h * WK;

    float* __restrict__ P = sWb[wrp];              // products [d*88 + 12*wl + k]
    float* __restrict__ N = P + Dn * PR;           // norms   [12*wl + k]

    // producer per-lane constants (q = position within 63-chunk)
    const int qa = lane;                           // round a: q in [0,32)
    const int qb = 32 + lane;                      // round b: q in [32,63)
    const bool vb = (qb < 63);
    const int offa = 12 * (qa / 9) + qa % 9;
    const int offb = 12 * (qb / 9) + qb % 9;
    // consumer per-lane constants (56 outputs per chunk = 8d x 7wl)
    const int ddA = lane & 7, wlA = lane >> 3;     // wl 0..3
    const bool vB = (lane < 24);
    const int ddB = lane & 7, wlB = 4 + (lane >> 3);
    // L2 prefetch covers full 4KB slab: lane -> (d = lane>>2, 128B line = lane&3)
    const long pfOff = (long)(lane >> 2) * strideD + 32 * (lane & 3);

    if (tid < Wn) sThr[tid] = 0u;

    // ---- Phase 1: warp-autonomous, 8-step pipeline (4 capsules x 2 chunks) ----
    float xa[Dn], xb[Dn];
    {   // prologue: load step 0 (capsule wrp, chunk 0)
        const float* g = base + (long)wrp * strideI;
        #pragma unroll
        for (int d = 0; d < Dn; ++d) xa[d] = g[d * strideD + qa];
        if (vb) {
            #pragma unroll
            for (int d = 0; d < Dn; ++d) xb[d] = g[d * strideD + qb];
        }
    }

    #pragma unroll
    for (int s = 0; s < 8; ++s) {
        const int i = wrp + 8 * (s >> 1), ch = s & 1;

        if (ch == 0 && s < 6)   // L2 warm: next-next capsule's slab
            pfL2(base + (long)(i + 8) * strideI + pfOff);

        // produce: norms + products into warp-private smem
        {
            float ss = 0.f;
            #pragma unroll
            for (int d = 0; d < Dn; ++d) ss += xa[d] * xa[d];
            const float nv = fsqrt_ap(ss);
            N[offa] = nv;
            #pragma unroll
            for (int d = 0; d < Dn; ++d) P[d * PR + offa] = nv * xa[d];
        }
        if (vb) {
            float ss = 0.f;
            #pragma unroll
            for (int d = 0; d < Dn; ++d) ss += xb[d] * xb[d];
            const float nv = fsqrt_ap(ss);
            N[offb] = nv;
            #pragma unroll
            for (int d = 0; d < Dn; ++d) P[d * PR + offb] = nv * xb[d];
        }

        // issue next step's 16 LDGs NOW -> in flight during consume
        if (s < 7) {
            const int sn = s + 1;
            const float* g = base + (long)(wrp + 8 * (sn >> 1)) * strideI
                           + 63 * (sn & 1);
            #pragma unroll
            for (int d = 0; d < Dn; ++d) xa[d] = g[d * strideD + qa];
            if (vb) {
                #pragma unroll
                for (int d = 0; d < Dn; ++d) xb[d] = g[d * strideD + qb];
            }
        }
        __syncwarp();

        // consume: xavg = (sum_k products) / (sum_k norms); pure smem
        {
            const float num = sum9(P + ddA * PR + 12 * wlA);
            const float den = sum9(N + 12 * wlA);
            sXavg[(7 * ch + wlA) * XW + i * Dn + ddA] = num * frcp_ap(den);
        }
        if (vB) {
            const float num = sum9(P + ddB * PR + 12 * wlB);
            const float den = sum9(N + 12 * wlB);
            sXavg[(7 * ch + wlB) * XW + i * Dn + ddB] = num * frcp_ap(den);
        }
        __syncwarp();   // P/N reused next step
    }
    __syncthreads();

    // ---- Phase 2: reductions over input capsules (float4 throughout) ----
    // nI[w][i] = || xavg[w][i][:] ||
    for (int p = tid; p < In * Wn; p += NT) {
        int w = p >> 5, i = p & 31;
        const float* xp = sXavg + w * XW + i * Dn;
        float4 lo = *(const float4*)(xp), hi = *(const float4*)(xp + 4);
        float s2 = lo.x*lo.x + lo.y*lo.y + lo.z*lo.z + lo.w*lo.w
                 + hi.x*hi.x + hi.y*hi.y + hi.z*hi.z + hi.w*hi.w;
        sNI[w * LW + i] = fsqrt_ap(s2);
    }
    __syncthreads();

    if (tid < Wn) {   // 1 / sum_i nI
        float sum = 0.f;
        #pragma unroll
        for (int q = 0; q < 8; ++q) {
            float4 v = *(const float4*)(sNI + tid * LW + 4 * q);
            sum += v.x + v.y + v.z + v.w;
        }
        sRsum[tid] = frcp_ap(sum);
    }
    __syncthreads();

    if (tid < 28) {   // consensus v[w][d]
        int w = tid >> 1, hf = tid & 1;
        float4 acc = {0.f, 0.f, 0.f, 0.f};
        #pragma unroll 8
        for (int i = 0; i < In; ++i) {
            float n = sNI[w * LW + i];
            float4 xv = *(const float4*)(sXavg + w * XW + i * Dn + 4 * hf);
            acc.x += n * xv.x; acc.y += n * xv.y;
            acc.z += n * xv.z; acc.w += n * xv.w;
        }
        float r = sRsum[w];
        float4 v = {acc.x * r, acc.y * r, acc.z * r, acc.w * r};
        *(float4*)(sV + w * Dn + 4 * hf) = v;
    }
    __syncthreads();

    // losses[w][i] = -<v[w], xavg[w][i]>
    for (int p = tid; p < In * Wn; p += NT) {
        int w = p >> 5, i = p & 31;
        const float* xp = sXavg + w * XW + i * Dn;
        float4 lo = *(const float4*)(xp), hi = *(const float4*)(xp + 4);
        float4 vl = *(const float4*)(sV + w * Dn);
        float4 vh = *(const float4*)(sV + w * Dn + 4);
        sLoss[w * LW + i] = -(vl.x*lo.x + vl.y*lo.y + vl.z*lo.z + vl.w*lo.w
                            + vh.x*hi.x + vh.y*hi.y + vh.z*hi.z + vh.w*hi.w);
    }
    __syncthreads();

    // kth-smallest threshold: thr = max{ v : #(x < v) <= SUBK-1 } == sorted[SUBK-1]
    if (tid < Dn * Wn) {
        int w = tid >> 3, iq = tid & 7;
        float4 cand = *(const float4*)(sLoss + w * LW + 4 * iq);
        int c0 = 0, c1 = 0, c2 = 0, c3 = 0;
        #pragma unroll
        for (int j = 0; j < 8; ++j) {
            float4 J = *(const float4*)(sLoss + w * LW + 4 * j);
            c0 += (J.x < cand.x) + (J.y < cand.x) + (J.z < cand.x) + (J.w < cand.x);
            c1 += (J.x < cand.y) + (J.y < cand.y) + (J.z < cand.y) + (J.w < cand.y);
            c2 += (J.x < cand.z) + (J.y < cand.z) + (J.z < cand.z) + (J.w < cand.z);
            c3 += (J.x < cand.w) + (J.y < cand.w) + (J.z < cand.w) + (J.w < cand.w);
        }
        if (c0 <= SUBK - 1) atomicMax(&sThr[w], fkey(cand.x));
        if (c1 <= SUBK - 1) atomicMax(&sThr[w], fkey(cand.y));
        if (c2 <= SUBK - 1) atomicMax(&sThr[w], fkey(cand.z));
        if (c3 <= SUBK - 1) atomicMax(&sThr[w], fkey(cand.w));
    }
    __syncthreads();

    if (tid < Wn) {   // masked denominator reciprocal
        const unsigned t = sThr[tid];
        float den = 0.f;
        #pragma unroll
        for (int q = 0; q < 8; ++q) {
            float4 L = *(const float4*)(sLoss + tid * LW + 4 * q);
            float4 Nv = *(const float4*)(sNI + tid * LW + 4 * q);
            den += (fkey(L.x) <= t ? Nv.x : 0.f) + (fkey(L.y) <= t ? Nv.y : 0.f)
                 + (fkey(L.z) <= t ? Nv.z : 0.f) + (fkey(L.w) <= t ? Nv.w : 0.f);
        }
        sRfin[tid] = frcp_ap(den);
    }
    __syncthreads();

    if (tid < 28) {   // masked re-average + store
        int w = tid >> 1, hf = tid & 1;
        const unsigned t = sThr[w];
        float4 acc = {0.f, 0.f, 0.f, 0.f};
        #pragma unroll 8
        for (int i = 0; i < In; ++i) {
            float l = sLoss[w * LW + i];
            float n = (fkey(l) <= t) ? sNI[w * LW + i] : 0.f;
            float4 xv = *(const float4*)(sXavg + w * XW + i * Dn + 4 * hf);
            acc.x += n * xv.x; acc.y += n * xv.y;
            acc.z += n * xv.z; acc.w += n * xv.w;
        }
        const float rf = sRfin[w];
        const long ob = ((long)b * On + o) * Dn;
        float vals[4] = {acc.x * rf, acc.y * rf, acc.z * rf, acc.w * rf};
        #pragma unroll
        for (int cc = 0; cc < 4; ++cc) {
            int d = 4 * hf + cc;
            out[(ob + d) * (Hn * Wn) + h * Wn + w] = vals[cc];
        }
    }
}

extern "C" void kernel_launch(void* const* d_in, const int* in_sizes, int n_in,
                              void* d_out, int out_size) {
    const float* x = (const float*)d_in[0];
    float* out = (float*)d_out;
    dim3 grid(Hn, On, Bn);   // 14 x 32 x 8 = 3584 CTAs
    caps_route_kernel<<<grid, NT>>>(x, out);
}

// round 13
// speedup vs baseline: 1.4152x; 1.0591x over previous
#include <cuda_runtime.h>

// x [B=8, I=32, O=32, D=8, H=14, W=14, kh=3, kw=3] fp32 -> out [B, O, D, H, W] fp32
namespace {
constexpr int Bn = 8, In = 32, On = 32, Dn = 8, Hn = 14, Wn = 14, Kn = 9;
constexpr int WK   = Wn * Kn;          // 126 positions
constexpr int NT   = 256;
constexpr int SUBK = 26;               // ceil(0.8 * 32)
constexpr int QS   = 12;               // PQ row stride (8 prod + norm + 3 pad), 48B: 16B-aligned rows
constexpr int WBUF = 64 * QS;          // 768 floats (63 rows used) per warp
constexpr int XW   = 260;              // sXavg w-stride: [w][i][d8] (16B-aligned)
constexpr int LW   = 36;               // sNI/sLoss w-stride: [w][i]
}

__device__ __forceinline__ float fsqrt_ap(float x) {
    float r; asm("sqrt.approx.f32 %0, %1;" : "=f"(r) : "f"(x)); return r;
}
__device__ __forceinline__ float frcp_ap(float x) {
    float r; asm("rcp.approx.f32 %0, %1;" : "=f"(r) : "f"(x)); return r;
}
__device__ __forceinline__ void pfL2(const void* p) {
    asm volatile("prefetch.global.L2 [%0];" :: "l"(p));
}
// Monotone float -> uint key: a <= b  <=>  fkey(a) <= fkey(b)
__device__ __forceinline__ unsigned fkey(float f) {
    unsigned u = __float_as_uint(f);
    return u ^ (unsigned)(((int)u >> 31) | 0x80000000);
}

__global__ void __launch_bounds__(NT, 5)
caps_route_kernel(const float* __restrict__ x, float* __restrict__ out) {
    const int h = blockIdx.x, o = blockIdx.y, b = blockIdx.z;
    const int tid = threadIdx.x;
    const int lane = tid & 31, wrp = tid >> 5;

    __shared__ __align__(16) float sWb[8][WBUF];   // warp-private PQ[q][12]
    __shared__ __align__(16) float sXavg[Wn * XW]; // [w][i][d8]
    __shared__ __align__(16) float sNI[Wn * LW];   // [w][i]
    __shared__ __align__(16) float sLoss[Wn * LW]; // [w][i]
    __shared__ __align__(16) float sV[Wn * Dn];    // [w][d]
    __shared__ float    sRsum[Wn];
    __shared__ unsigned sThr[Wn];
    __shared__ float    sRfin[Wn];

    const long strideD = (long)Hn * Wn * Kn;       // 1764
    const long strideO = Dn * strideD;             // 14112
    const long strideI = On * strideO;             // 451584
    const long strideB = In * strideI;             // 14450688
    const float* base = x + (long)b * strideB + (long)o * strideO + (long)h * WK;

    float* __restrict__ PQ = sWb[wrp];             // [q][12]: prod d0..7, norm@8

    // producer: q in [0,63) per chunk; round a = lane, round b = 32+lane
    const int qa = lane;
    const int qb = 32 + lane;
    const bool vb = (qb < 63);
    // consumer: 28 lanes, lane = dp*7 + wl  (dp = d-pair 0..3, wl = 0..6)
    const bool vC = (lane < 28);
    const int dpC = lane / 7, wlC = lane - 7 * dpC;
    // L2 prefetch: lane -> (d = lane>>2, 128B line = lane&3) covers full 4KB slab
    const long pfOff = (long)(lane >> 2) * strideD + 32 * (lane & 3);

    if (tid < Wn) sThr[tid] = 0u;

    // ---- Phase 1: warp-autonomous, 8-step pipeline (4 capsules x 2 chunks) ----
    float xa[Dn], xb[Dn];
    {   // prologue: load step 0 (capsule wrp, chunk 0)
        const float* g = base + (long)wrp * strideI;
        #pragma unroll
        for (int d = 0; d < Dn; ++d) xa[d] = g[d * strideD + qa];
        if (vb) {
            #pragma unroll
            for (int d = 0; d < Dn; ++d) xb[d] = g[d * strideD + qb];
        }
    }

    #pragma unroll
    for (int s = 0; s < 8; ++s) {
        const int i = wrp + 8 * (s >> 1), ch = s & 1;

        if (ch == 0 && s < 6)   // L2 warm: next capsule's slab
            pfL2(base + (long)(i + 8) * strideI + pfOff);

        // produce: per position, 2xSTS.128 + STS.32 (3 stores)
        {
            float ss = 0.f;
            #pragma unroll
            for (int d = 0; d < Dn; ++d) ss += xa[d] * xa[d];
            const float nv = fsqrt_ap(ss);
            float* row = PQ + qa * QS;
            float4 lo = {nv * xa[0], nv * xa[1], nv * xa[2], nv * xa[3]};
            float4 hi = {nv * xa[4], nv * xa[5], nv * xa[6], nv * xa[7]};
            *(float4*)(row)     = lo;
            *(float4*)(row + 4) = hi;
            row[8] = nv;
        }
        if (vb) {
            float ss = 0.f;
            #pragma unroll
            for (int d = 0; d < Dn; ++d) ss += xb[d] * xb[d];
            const float nv = fsqrt_ap(ss);
            float* row = PQ + qb * QS;
            float4 lo = {nv * xb[0], nv * xb[1], nv * xb[2], nv * xb[3]};
            float4 hi = {nv * xb[4], nv * xb[5], nv * xb[6], nv * xb[7]};
            *(float4*)(row)     = lo;
            *(float4*)(row + 4) = hi;
            row[8] = nv;
        }

        // issue next step's 16 LDGs NOW -> in flight during consume
        if (s < 7) {
            const int sn = s + 1;
            const float* g = base + (long)(wrp + 8 * (sn >> 1)) * strideI
                           + 63 * (sn & 1);
            #pragma unroll
            for (int d = 0; d < Dn; ++d) xa[d] = g[d * strideD + qa];
            if (vb) {
                #pragma unroll
                for (int d = 0; d < Dn; ++d) xb[d] = g[d * strideD + qb];
            }
        }
        __syncwarp();

        // consume: 28 lanes cover all 56 (d-pair, w) outputs of this chunk
        if (vC) {
            const float* rb = PQ + 9 * wlC * QS + 2 * dpC;
            float2 num = {0.f, 0.f};
            float den = 0.f;
            #pragma unroll
            for (int k = 0; k < Kn; ++k) {
                float2 p2 = *(const float2*)(rb + k * QS);
                num.x += p2.x; num.y += p2.y;
                den += rb[k * QS + (8 - 2 * dpC)];   // PQ[q][8] (norm)
            }
            const float r = frcp_ap(den);
            float2 res = {num.x * r, num.y * r};
            *(float2*)(sXavg + (7 * ch + wlC) * XW + i * Dn + 2 * dpC) = res;
        }
        __syncwarp();   // PQ reused next step
    }
    __syncthreads();

    // ---- Phase 2: reductions over input capsules (float4 throughout) ----
    // nI[w][i] = || xavg[w][i][:] ||
    for (int p = tid; p < In * Wn; p += NT) {
        int w = p >> 5, i = p & 31;
        const float* xp = sXavg + w * XW + i * Dn;
        float4 lo = *(const float4*)(xp), hi = *(const float4*)(xp + 4);
        float s2 = lo.x*lo.x + lo.y*lo.y + lo.z*lo.z + lo.w*lo.w
                 + hi.x*hi.x + hi.y*hi.y + hi.z*hi.z + hi.w*hi.w;
        sNI[w * LW + i] = fsqrt_ap(s2);
    }
    __syncthreads();

    if (tid < Wn) {   // 1 / sum_i nI
        float sum = 0.f;
        #pragma unroll
        for (int q = 0; q < 8; ++q) {
            float4 v = *(const float4*)(sNI + tid * LW + 4 * q);
            sum += v.x + v.y + v.z + v.w;
        }
        sRsum[tid] = frcp_ap(sum);
    }
    __syncthreads();

    if (tid < 28) {   // consensus v[w][d]
        int w = tid >> 1, hf = tid & 1;
        float4 acc = {0.f, 0.f, 0.f, 0.f};
        #pragma unroll 8
        for (int i = 0; i < In; ++i) {
            float n = sNI[w * LW + i];
            float4 xv = *(const float4*)(sXavg + w * XW + i * Dn + 4 * hf);
            acc.x += n * xv.x; acc.y += n * xv.y;
            acc.z += n * xv.z; acc.w += n * xv.w;
        }
        float r = sRsum[w];
        float4 v = {acc.x * r, acc.y * r, acc.z * r, acc.w * r};
        *(float4*)(sV + w * Dn + 4 * hf) = v;
    }
    __syncthreads();

    // losses[w][i] = -<v[w], xavg[w][i]>
    for (int p = tid; p < In * Wn; p += NT) {
        int w = p >> 5, i = p & 31;
        const float* xp = sXavg + w * XW + i * Dn;
        float4 lo = *(const float4*)(xp), hi = *(const float4*)(xp + 4);
        float4 vl = *(const float4*)(sV + w * Dn);
        float4 vh = *(const float4*)(sV + w * Dn + 4);
        sLoss[w * LW + i] = -(vl.x*lo.x + vl.y*lo.y + vl.z*lo.z + vl.w*lo.w
                            + vh.x*hi.x + vh.y*hi.y + vh.z*hi.z + vh.w*hi.w);
    }
    __syncthreads();

    // kth-smallest threshold: thr = max{ v : #(x < v) <= SUBK-1 } == sorted[SUBK-1]
    if (tid < Dn * Wn) {
        int w = tid >> 3, iq = tid & 7;
        float4 cand = *(const float4*)(sLoss + w * LW + 4 * iq);
        int c0 = 0, c1 = 0, c2 = 0, c3 = 0;
        #pragma unroll
        for (int j = 0; j < 8; ++j) {
            float4 J = *(const float4*)(sLoss + w * LW + 4 * j);
            c0 += (J.x < cand.x) + (J.y < cand.x) + (J.z < cand.x) + (J.w < cand.x);
            c1 += (J.x < cand.y) + (J.y < cand.y) + (J.z < cand.y) + (J.w < cand.y);
            c2 += (J.x < cand.z) + (J.y < cand.z) + (J.z < cand.z) + (J.w < cand.z);
            c3 += (J.x < cand.w) + (J.y < cand.w) + (J.z < cand.w) + (J.w < cand.w);
        }
        if (c0 <= SUBK - 1) atomicMax(&sThr[w], fkey(cand.x));
        if (c1 <= SUBK - 1) atomicMax(&sThr[w], fkey(cand.y));
        if (c2 <= SUBK - 1) atomicMax(&sThr[w], fkey(cand.z));
        if (c3 <= SUBK - 1) atomicMax(&sThr[w], fkey(cand.w));
    }
    __syncthreads();

    if (tid < Wn) {   // masked denominator reciprocal
        const unsigned t = sThr[tid];
        float den = 0.f;
        #pragma unroll
        for (int q = 0; q < 8; ++q) {
            float4 L = *(const float4*)(sLoss + tid * LW + 4 * q);
            float4 Nv = *(const float4*)(sNI + tid * LW + 4 * q);
            den += (fkey(L.x) <= t ? Nv.x : 0.f) + (fkey(L.y) <= t ? Nv.y : 0.f)
                 + (fkey(L.z) <= t ? Nv.z : 0.f) + (fkey(L.w) <= t ? Nv.w : 0.f);
        }
        sRfin[tid] = frcp_ap(den);
    }
    __syncthreads();

    if (tid < 28) {   // masked re-average + store
        int w = tid >> 1, hf = tid & 1;
        const unsigned t = sThr[w];
        float4 acc = {0.f, 0.f, 0.f, 0.f};
        #pragma unroll 8
        for (int i = 0; i < In; ++i) {
            float l = sLoss[w * LW + i];
            float n = (fkey(l) <= t) ? sNI[w * LW + i] : 0.f;
            float4 xv = *(const float4*)(sXavg + w * XW + i * Dn + 4 * hf);
            acc.x += n * xv.x; acc.y += n * xv.y;
            acc.z += n * xv.z; acc.w += n * xv.w;
        }
        const float rf = sRfin[w];
        const long ob = ((long)b * On + o) * Dn;
        float vals[4] = {acc.x * rf, acc.y * rf, acc.z * rf, acc.w * rf};
        #pragma unroll
        for (int cc = 0; cc < 4; ++cc) {
            int d = 4 * hf + cc;
            out[(ob + d) * (Hn * Wn) + h * Wn + w] = vals[cc];
        }
    }
}

extern "C" void kernel_launch(void* const* d_in, const int* in_sizes, int n_in,
                              void* d_out, int out_size) {
    const float* x = (const float*)d_in[0];
    float* out = (float*)d_out;
    dim3 grid(Hn, On, Bn);   // 14 x 32 x 8 = 3584 CTAs
    caps_route_kernel<<<grid, NT>>>(x, out);
}